// round 9
// baseline (speedup 1.0000x reference)
#include <cuda_runtime.h>
#include <cuda_fp16.h>
#include <cstdint>

#define S_LEN 256
#define BATCH 16
#define HID   1024
#define G3    3072
#define SB    4096
#define NTOK  32000

// ---------------------------------------------------------------------------
// Static scratch (allocation-free per harness rules)
// ---------------------------------------------------------------------------
__device__ __half g_wih[2][G3 * HID];
__device__ __half g_whh[2][G3 * HID];
__device__ __half g_wattn[2][HID * HID];
__device__ __half g_wdec[(size_t)NTOK * 2 * HID];
__device__ __half g_xemb[2][SB * HID];
__device__ float  g_xg[2][(size_t)SB * G3];
__device__ __half g_outh[2][SB * HID];
__device__ float  g_tmp[2][(size_t)SB * HID];
__device__ float  g_sc[2][SB];
__device__ __half g_ctx[(size_t)SB * 2 * HID];
__device__ __half g_h[2][2 * BATCH * HID];
__device__ unsigned g_bar[2];

// ---------------------------------------------------------------------------
// Primitives (mma.sync / ldmatrix / cp.async only — tcgen05 unavailable on
// this bench's compute_103 virtual target)
// ---------------------------------------------------------------------------
__device__ __forceinline__ uint32_t sm_u32(const void* p) {
    return (uint32_t)__cvta_generic_to_shared(p);
}

__device__ __forceinline__ void mma16816(float* c, const uint32_t* a,
                                         uint32_t b0, uint32_t b1) {
    asm volatile(
        "mma.sync.aligned.m16n8k16.row.col.f32.f16.f16.f32 "
        "{%0,%1,%2,%3}, {%4,%5,%6,%7}, {%8,%9}, {%0,%1,%2,%3};"
        : "+f"(c[0]), "+f"(c[1]), "+f"(c[2]), "+f"(c[3])
        : "r"(a[0]), "r"(a[1]), "r"(a[2]), "r"(a[3]), "r"(b0), "r"(b1));
}

__device__ __forceinline__ void ldsm4(uint32_t* r, uint32_t addr) {
    asm volatile(
        "ldmatrix.sync.aligned.m8n8.x4.shared.b16 {%0,%1,%2,%3}, [%4];"
        : "=r"(r[0]), "=r"(r[1]), "=r"(r[2]), "=r"(r[3]) : "r"(addr));
}

__device__ __forceinline__ void cp16s(uint32_t s, const void* g) {
    asm volatile("cp.async.cg.shared.global [%0], [%1], 16;" :: "r"(s), "l"(g));
}
#define CP_COMMIT() asm volatile("cp.async.commit_group;" ::: "memory")
#define CP_WAIT1()  asm volatile("cp.async.wait_group 1;" ::: "memory")

// ---------------------------------------------------------------------------
// fp32 -> fp16 conversion (float4 vectorized)
// ---------------------------------------------------------------------------
__global__ void k_cvt(const float* __restrict__ src, __half* __restrict__ dst, int n4) {
    int i = blockIdx.x * blockDim.x + threadIdx.x;
    int st = gridDim.x * blockDim.x;
    __half2* d2 = reinterpret_cast<__half2*>(dst);
    for (; i < n4; i += st) {
        float4 v = reinterpret_cast<const float4*>(src)[i];
        d2[2 * i]     = __floats2half2_rn(v.x, v.y);
        d2[2 * i + 1] = __floats2half2_rn(v.z, v.w);
    }
}

__global__ void k_hinit(const float* __restrict__ hl, const float* __restrict__ hr) {
    int t = threadIdx.x;
    if (t < 2) g_bar[t] = 0u;
    for (int i = t; i < BATCH * HID; i += blockDim.x) {
        g_h[0][i] = __float2half(hl[i]);
        g_h[1][i] = __float2half(hr[i]);
    }
}

__global__ void k_embed(const int* __restrict__ dl, const int* __restrict__ dr,
                        const float* __restrict__ emb, __half* __restrict__ xemb) {
    int row = blockIdx.x;
    int dir = row >> 12;
    int r   = row & (SB - 1);
    int s   = r >> 4, b = r & 15;
    int tok = dir ? dr[(S_LEN - 1 - s) * BATCH + b] : dl[r];
    const float2* src = reinterpret_cast<const float2*>(emb + (size_t)tok * HID);
    __half2* dst = reinterpret_cast<__half2*>(xemb + (size_t)dir * SB * HID + (size_t)r * HID);
    for (int i = threadIdx.x; i < HID / 2; i += blockDim.x) {
        float2 v = src[i];
        dst[i] = __floats2half2_rn(v.x, v.y);
    }
}

// ---------------------------------------------------------------------------
// fp16 GEMM: C[M,N] = A[M,K]*B[N,K]^T + bias
// 128x256x32 CTA tile, 256 threads (2x4 warp grid, 64x64 warp tile),
// 3-stage cp.async pipeline, one __syncthreads per k-iter.
// Requires M%128==0, N%256==0, K%32==0.
// ---------------------------------------------------------------------------
#define SSTR 40
#define A_ST (128 * SSTR)                 // halfs per A stage
#define B_ST (256 * SSTR)                 // halfs per B stage
#define STG  (A_ST + B_ST)                // 15360 halfs = 30720 B per stage
#define GSMEM (3 * STG * 2)               // 92160 B

__global__ void __launch_bounds__(256, 1) k_gemm(
    const __half* __restrict__ A, const __half* __restrict__ B,
    const float* __restrict__ bias, float* __restrict__ C, int N, int K)
{
    extern __shared__ __half sm[];
    const int tid = threadIdx.x, wid = tid >> 5, lane = tid & 31;
    const int wm = (wid & 1) * 64, wn = (wid >> 1) * 64;
    const int m0 = blockIdx.x * 128, n0 = blockIdx.y * 256;

    float acc[4][8][4];
#pragma unroll
    for (int mi = 0; mi < 4; mi++)
#pragma unroll
        for (int ni = 0; ni < 8; ni++)
#pragma unroll
            for (int q = 0; q < 4; q++) acc[mi][ni][q] = 0.f;

    // ldmatrix base addresses (stage 0); add byte stage offset per iter
    const int ar = ((lane >> 3) & 1) * 8 + (lane & 7);
    const int acb = (lane >> 4) * 8;
    uint32_t a_sm[4];
#pragma unroll
    for (int mi = 0; mi < 4; mi++)
        a_sm[mi] = sm_u32(&sm[(wm + mi * 16 + ar) * SSTR + acb]);
    const int br = (lane >> 4) * 8 + (lane & 7);
    const int bcb = ((lane >> 3) & 1) * 8;
    uint32_t b_sm[4];
#pragma unroll
    for (int nj = 0; nj < 4; nj++)
        b_sm[nj] = sm_u32(&sm[A_ST + (wn + nj * 16 + br) * SSTR + bcb]);

    // per-thread staging coords
    const int lr = tid >> 2, lc = (tid & 3) * 8;
    const __half* Ag = A + (size_t)(m0 + lr) * K + lc;
    const __half* Bg = B + (size_t)(n0 + lr) * K + lc;
    const uint32_t sA = sm_u32(&sm[lr * SSTR + lc]);
    const uint32_t sB = sm_u32(&sm[A_ST + lr * SSTR + lc]);

    const int niter = K >> 5;

#define LOAD_STAGE(s)                                                          \
    do {                                                                       \
        const uint32_t off_ = (uint32_t)((s) % 3) * (STG * 2);                 \
        const int k0_ = (s) << 5;                                              \
        cp16s(sA + off_,                    Ag + k0_);                         \
        cp16s(sA + off_ + 64 * SSTR * 2,    Ag + (size_t)64 * K + k0_);        \
        cp16s(sB + off_,                    Bg + k0_);                         \
        cp16s(sB + off_ + 64 * SSTR * 2,    Bg + (size_t)64 * K + k0_);        \
        cp16s(sB + off_ + 128 * SSTR * 2,   Bg + (size_t)128 * K + k0_);       \
        cp16s(sB + off_ + 192 * SSTR * 2,   Bg + (size_t)192 * K + k0_);       \
    } while (0)

    LOAD_STAGE(0);
    CP_COMMIT();
    if (niter > 1) { LOAD_STAGE(1); }
    CP_COMMIT();

    for (int it = 0; it < niter; it++) {
        CP_WAIT1();
        __syncthreads();
        const uint32_t off = (uint32_t)(it % 3) * (STG * 2);
#pragma unroll
        for (int kk = 0; kk < 2; kk++) {
            uint32_t af[4][4], bf[4][4];
#pragma unroll
            for (int mi = 0; mi < 4; mi++) ldsm4(af[mi], a_sm[mi] + off + kk * 32);
#pragma unroll
            for (int nj = 0; nj < 4; nj++) ldsm4(bf[nj], b_sm[nj] + off + kk * 32);
#pragma unroll
            for (int mi = 0; mi < 4; mi++)
#pragma unroll
                for (int ni = 0; ni < 8; ni++)
                    mma16816(acc[mi][ni], af[mi],
                             bf[ni >> 1][(ni & 1) * 2], bf[ni >> 1][(ni & 1) * 2 + 1]);
        }
        if (it + 2 < niter) { LOAD_STAGE(it + 2); }
        CP_COMMIT();
    }
#undef LOAD_STAGE

    const int g = lane >> 2, t2 = (lane & 3) * 2;
#pragma unroll
    for (int mi = 0; mi < 4; mi++)
#pragma unroll
        for (int ni = 0; ni < 8; ni++) {
            int row = m0 + wm + mi * 16 + g;
            int col = n0 + wn + ni * 8 + t2;
            float b0 = bias[col], b1 = bias[col + 1];
            float2 r0 = make_float2(acc[mi][ni][0] + b0, acc[mi][ni][1] + b1);
            *reinterpret_cast<float2*>(&C[(size_t)row * N + col]) = r0;
            float2 r1 = make_float2(acc[mi][ni][2] + b0, acc[mi][ni][3] + b1);
            *reinterpret_cast<float2*>(&C[(size_t)(row + 8) * N + col]) = r1;
        }
}

// ---------------------------------------------------------------------------
// Persistent GRU (unchanged): 128 CTAs, Whh register-resident.
// ---------------------------------------------------------------------------
#define SPAD 1032

__global__ void __launch_bounds__(384, 1) k_gru(
    const float* __restrict__ bhh_l, const float* __restrict__ bhh_r)
{
    const int dir = blockIdx.x >> 6;
    const int j0  = (blockIdx.x & 63) * 16;
    const float* bhh = dir ? bhh_r : bhh_l;

    __shared__ __half As[16 * SPAD];
    __shared__ float red[12][16][8];

    const int tid = threadIdx.x, wid = tid >> 5, lane = tid & 31;
    const int gw = wid % 6, kh = wid / 6;
    const int gate = gw >> 1, jh = gw & 1;
    const int g = lane >> 2, t2 = (lane & 3) * 2;
    const int nrow = gate * HID + j0 + jh * 8 + g;
    const int kbase = kh * 512;

    uint32_t rb0[32], rb1[32];
    const __half* wr = g_whh[dir] + (size_t)nrow * HID + kbase + t2;
#pragma unroll
    for (int c = 0; c < 32; c++) {
        rb0[c] = *reinterpret_cast<const uint32_t*>(wr + c * 16);
        rb1[c] = *reinterpret_cast<const uint32_t*>(wr + c * 16 + 8);
    }

    const int ar = ((lane >> 3) & 1) * 8 + (lane & 7);
    const uint32_t a_sm = (uint32_t)__cvta_generic_to_shared(
        &As[ar * SPAD + (lane >> 4) * 8 + kbase]);

    __half* hw = g_h[dir];
    unsigned* barp = &g_bar[dir];
    const float* xgp = g_xg[dir];

#pragma unroll 1
    for (int s = 0; s < S_LEN; s++) {
        const int cur = s & 1;
        const uint4* hsrc = reinterpret_cast<const uint4*>(hw + cur * BATCH * HID);
        for (int i = tid; i < 2048; i += 384) {
            int r = i >> 7, c8 = (i & 127) * 8;
            *reinterpret_cast<uint4*>(&As[r * SPAD + c8]) = __ldcg(&hsrc[r * 128 + (i & 127)]);
        }
        __syncthreads();

        float acc[4] = {0.f, 0.f, 0.f, 0.f};
#pragma unroll
        for (int c = 0; c < 32; c++) {
            uint32_t af[4];
            ldsm4(af, a_sm + c * 32);
            mma16816(acc, af, rb0[c], rb1[c]);
        }
        red[wid][g][t2]         = acc[0];
        red[wid][g][t2 + 1]     = acc[1];
        red[wid][g + 8][t2]     = acc[2];
        red[wid][g + 8][t2 + 1] = acc[3];
        __syncthreads();

        for (int idx = tid; idx < 256; idx += 384) {
            int b = idx >> 4, jj = idx & 15, j = j0 + jj;
            int w0 = jj >> 3, c7 = jj & 7;
            float hr = red[w0][b][c7]      + red[6 + w0][b][c7]  + bhh[j];
            float hz = red[2 + w0][b][c7]  + red[8 + w0][b][c7]  + bhh[HID + j];
            float hn = red[4 + w0][b][c7]  + red[10 + w0][b][c7] + bhh[2 * HID + j];
            const float* xr = &xgp[(size_t)(s * 16 + b) * G3 + j];
            float r = 1.f / (1.f + expf(-(xr[0] + hr)));
            float z = 1.f / (1.f + expf(-(xr[HID] + hz)));
            float n = tanhf(xr[2 * HID] + r * hn);
            float hp = __half2float(As[b * SPAD + j]);
            float h = (1.f - z) * n + z * hp;
            hw[(cur ^ 1) * BATCH * HID + b * HID + j] = __float2half(h);
            g_outh[dir][(s * 16 + b) * HID + j] = __float2half(h);
        }
        __syncthreads();

        if (tid == 0) {
            __threadfence();
            atomicAdd(barp, 1u);
            unsigned tgt = 64u * (unsigned)(s + 1);
            while (*(volatile unsigned*)barp < tgt) __nanosleep(64);
        }
        __syncthreads();
    }
}

// ---------------------------------------------------------------------------
// Attention scores / exp / cumulative context
// ---------------------------------------------------------------------------
__global__ void k_score(const float* __restrict__ tmp,
                        const float* __restrict__ vl, const float* __restrict__ bvl,
                        const float* __restrict__ vr, const float* __restrict__ bvr,
                        float* __restrict__ sc) {
    int dir = blockIdx.x >> 9;
    int row = (blockIdx.x & 511) * 8 + (threadIdx.x >> 5);
    int lane = threadIdx.x & 31;
    const float* v = dir ? vr : vl;
    float bv = dir ? bvr[0] : bvl[0];
    const float* t = tmp + (size_t)dir * SB * HID + (size_t)row * HID;
    float s = 0.f;
    for (int j = lane; j < HID; j += 32) s += tanhf(t[j]) * v[j];
#pragma unroll
    for (int o = 16; o; o >>= 1) s += __shfl_xor_sync(0xffffffffu, s, o);
    if (lane == 0) sc[dir * SB + row] = s + bv;
}

__global__ void k_e(float* __restrict__ sc) {
    int dir = blockIdx.x >> 4, b = blockIdx.x & 15, lane = threadIdx.x;
    float v[8];
    float m = -1e30f;
#pragma unroll
    for (int i = 0; i < 8; i++) {
        v[i] = sc[dir * SB + (lane * 8 + i) * 16 + b];
        m = fmaxf(m, v[i]);
    }
#pragma unroll
    for (int o = 16; o; o >>= 1) m = fmaxf(m, __shfl_xor_sync(0xffffffffu, m, o));
#pragma unroll
    for (int i = 0; i < 8; i++)
        sc[dir * SB + (lane * 8 + i) * 16 + b] = expf(v[i] - m);
}

__global__ void k_cumsum(const float* __restrict__ sc,
                         const __half* __restrict__ outh, __half* __restrict__ ctx) {
    int bid = blockIdx.x;
    int dir = bid >> 7, rem = bid & 127;
    int b = rem >> 3, chunk = rem & 7;
    int j = chunk * 128 + threadIdx.x;
    float acc = 0.f, den = 0.f;
    for (int s = 0; s < S_LEN; s++) {
        float e = sc[dir * SB + s * 16 + b];
        float o = __half2float(outh[(size_t)dir * SB * HID + (s * 16 + b) * HID + j]);
        acc += e * o;
        den += e;
        int row = dir ? (S_LEN - 1 - s) : s;
        ctx[(size_t)(row * 16 + b) * 2 * HID + dir * HID + j] = __float2half(acc / den);
    }
}

// ---------------------------------------------------------------------------
// Launch sequence
// ---------------------------------------------------------------------------
extern "C" void kernel_launch(void* const* d_in, const int* in_sizes, int n_in,
                              void* d_out, int out_size) {
    const int*   dl      = (const int*)d_in[0];
    const int*   dr      = (const int*)d_in[1];
    const float* hl      = (const float*)d_in[2];
    const float* hr      = (const float*)d_in[3];
    const float* emb     = (const float*)d_in[4];
    const float* wih_l   = (const float*)d_in[5];
    const float* whh_l   = (const float*)d_in[6];
    const float* bih_l   = (const float*)d_in[7];
    const float* bhh_l   = (const float*)d_in[8];
    const float* wih_r   = (const float*)d_in[9];
    const float* whh_r   = (const float*)d_in[10];
    const float* bih_r   = (const float*)d_in[11];
    const float* bhh_r   = (const float*)d_in[12];
    const float* wattn_l = (const float*)d_in[13];
    const float* battn_l = (const float*)d_in[14];
    const float* vl      = (const float*)d_in[15];
    const float* bvl     = (const float*)d_in[16];
    const float* wattn_r = (const float*)d_in[17];
    const float* battn_r = (const float*)d_in[18];
    const float* vr      = (const float*)d_in[19];
    const float* bvr     = (const float*)d_in[20];
    const float* wdec    = (const float*)d_in[21];
    const float* bdec    = (const float*)d_in[22];
    float* out = (float*)d_out;

    void* p;
    cudaGetSymbolAddress(&p, g_wih);   __half* wih    = (__half*)p;
    cudaGetSymbolAddress(&p, g_whh);   __half* whh    = (__half*)p;
    cudaGetSymbolAddress(&p, g_wattn); __half* wattn  = (__half*)p;
    cudaGetSymbolAddress(&p, g_wdec);  __half* wdec16 = (__half*)p;
    cudaGetSymbolAddress(&p, g_xemb);  __half* xemb   = (__half*)p;
    cudaGetSymbolAddress(&p, g_xg);    float*  xg     = (float*)p;
    cudaGetSymbolAddress(&p, g_outh);  __half* outh   = (__half*)p;
    cudaGetSymbolAddress(&p, g_tmp);   float*  tmp    = (float*)p;
    cudaGetSymbolAddress(&p, g_sc);    float*  sc     = (float*)p;
    cudaGetSymbolAddress(&p, g_ctx);   __half* ctx    = (__half*)p;

    cudaFuncSetAttribute(k_gemm, cudaFuncAttributeMaxDynamicSharedMemorySize, GSMEM);

    k_hinit<<<1, 256>>>(hl, hr);
    k_cvt<<<512, 256>>>(wih_l,   wih,               G3 * HID / 4);
    k_cvt<<<512, 256>>>(whh_l,   whh,               G3 * HID / 4);
    k_cvt<<<512, 256>>>(wih_r,   wih + G3 * HID,    G3 * HID / 4);
    k_cvt<<<512, 256>>>(whh_r,   whh + G3 * HID,    G3 * HID / 4);
    k_cvt<<<256, 256>>>(wattn_l, wattn,              HID * HID / 4);
    k_cvt<<<256, 256>>>(wattn_r, wattn + HID * HID,  HID * HID / 4);
    k_cvt<<<2048, 256>>>(wdec,   wdec16,             NTOK * 2 * HID / 4);
    k_embed<<<8192, 128>>>(dl, dr, emb, xemb);

    // xg[dir] = xemb[dir] @ Wih^T + bih   [4096, 3072]
    k_gemm<<<dim3(32, 12), 256, GSMEM>>>(xemb,            wih,            bih_l, xg,                    G3, HID);
    k_gemm<<<dim3(32, 12), 256, GSMEM>>>(xemb + SB * HID, wih + G3 * HID, bih_r, xg + (size_t)SB * G3,  G3, HID);

    k_gru<<<128, 384>>>(bhh_l, bhh_r);

    // tmp[dir] = outh[dir] @ Wattn^T + battn   [4096, 1024]
    k_gemm<<<dim3(32, 4), 256, GSMEM>>>(outh,            wattn,             battn_l, tmp,            HID, HID);
    k_gemm<<<dim3(32, 4), 256, GSMEM>>>(outh + SB * HID, wattn + HID * HID, battn_r, tmp + SB * HID, HID, HID);

    k_score<<<1024, 256>>>(tmp, vl, bvl, vr, bvr, sc);
    k_e<<<32, 32>>>(sc);
    k_cumsum<<<256, 128>>>(sc, outh, ctx);

    // decoded = ctx @ Wdec^T + bdec   [4096, 32000]
    k_gemm<<<dim3(32, 125), 256, GSMEM>>>(ctx, wdec16, bdec, out, NTOK, 2 * HID);
}

// round 10
// speedup vs baseline: 1.0166x; 1.0166x over previous
#include <cuda_runtime.h>
#include <cuda_fp16.h>
#include <cstdint>

#define S_LEN 256
#define BATCH 16
#define HID   1024
#define G3    3072
#define SB    4096
#define NTOK  32000

// ---------------------------------------------------------------------------
// Static scratch (allocation-free per harness rules)
// ---------------------------------------------------------------------------
__device__ __half g_wih[2][G3 * HID];
__device__ __half g_whh[2][G3 * HID];
__device__ __half g_wattn[2][HID * HID];
__device__ __half g_wdec[(size_t)NTOK * 2 * HID];
__device__ __half g_xemb[2][SB * HID];
__device__ float  g_xg[2][(size_t)SB * G3];
__device__ __half g_outh[2][SB * HID];
__device__ float  g_tmp[2][(size_t)SB * HID];
__device__ float  g_sc[2][SB];
__device__ __half g_ctx[(size_t)SB * 2 * HID];
__device__ __half g_h[2][2 * BATCH * HID];
__device__ unsigned g_bar[2];

// ---------------------------------------------------------------------------
// Primitives (mma.sync / ldmatrix / cp.async — tcgen05 is unavailable on the
// bench's compute_103 virtual target, confirmed R7)
// ---------------------------------------------------------------------------
__device__ __forceinline__ uint32_t sm_u32(const void* p) {
    return (uint32_t)__cvta_generic_to_shared(p);
}

__device__ __forceinline__ void mma16816(float* c, const uint32_t* a,
                                         uint32_t b0, uint32_t b1) {
    asm volatile(
        "mma.sync.aligned.m16n8k16.row.col.f32.f16.f16.f32 "
        "{%0,%1,%2,%3}, {%4,%5,%6,%7}, {%8,%9}, {%0,%1,%2,%3};"
        : "+f"(c[0]), "+f"(c[1]), "+f"(c[2]), "+f"(c[3])
        : "r"(a[0]), "r"(a[1]), "r"(a[2]), "r"(a[3]), "r"(b0), "r"(b1));
}

__device__ __forceinline__ void ldsm4(uint32_t* r, uint32_t addr) {
    asm volatile(
        "ldmatrix.sync.aligned.m8n8.x4.shared.b16 {%0,%1,%2,%3}, [%4];"
        : "=r"(r[0]), "=r"(r[1]), "=r"(r[2]), "=r"(r[3]) : "r"(addr));
}

__device__ __forceinline__ void cp16s(uint32_t s, const void* g) {
    asm volatile("cp.async.cg.shared.global [%0], [%1], 16;" :: "r"(s), "l"(g));
}
#define CP_COMMIT() asm volatile("cp.async.commit_group;" ::: "memory")
#define CP_WAIT1()  asm volatile("cp.async.wait_group 1;" ::: "memory")

// ---------------------------------------------------------------------------
// fp32 -> fp16 conversion: 8 elems/thread, LDG.128 x2 + STG.128 x1
// ---------------------------------------------------------------------------
__device__ __forceinline__ void cvt8(const float4* __restrict__ s4,
                                     uint4* __restrict__ d4, int i) {
    float4 a = s4[2 * i], b = s4[2 * i + 1];
    __half2 h0 = __floats2half2_rn(a.x, a.y);
    __half2 h1 = __floats2half2_rn(a.z, a.w);
    __half2 h2 = __floats2half2_rn(b.x, b.y);
    __half2 h3 = __floats2half2_rn(b.z, b.w);
    uint4 o;
    o.x = *reinterpret_cast<uint32_t*>(&h0);
    o.y = *reinterpret_cast<uint32_t*>(&h1);
    o.z = *reinterpret_cast<uint32_t*>(&h2);
    o.w = *reinterpret_cast<uint32_t*>(&h3);
    d4[i] = o;
}

__global__ void k_cvt(const float* __restrict__ src, __half* __restrict__ dst, int n8) {
    int i = blockIdx.x * blockDim.x + threadIdx.x;
    int st = gridDim.x * blockDim.x;
    const float4* s4 = reinterpret_cast<const float4*>(src);
    uint4* d4 = reinterpret_cast<uint4*>(dst);
    for (; i < n8; i += st) cvt8(s4, d4, i);
}

__global__ void k_hinit(const float* __restrict__ hl, const float* __restrict__ hr) {
    int t = threadIdx.x;
    if (t < 2) g_bar[t] = 0u;
    for (int i = t; i < BATCH * HID; i += blockDim.x) {
        g_h[0][i] = __float2half(hl[i]);
        g_h[1][i] = __float2half(hr[i]);
    }
}

__global__ void k_embed(const int* __restrict__ dl, const int* __restrict__ dr,
                        const float* __restrict__ emb, __half* __restrict__ xemb) {
    int row = blockIdx.x;
    int dir = row >> 12;
    int r   = row & (SB - 1);
    int s   = r >> 4, b = r & 15;
    int tok = dir ? dr[(S_LEN - 1 - s) * BATCH + b] : dl[r];
    const float4* src = reinterpret_cast<const float4*>(emb + (size_t)tok * HID);
    uint4* dst = reinterpret_cast<uint4*>(xemb + (size_t)dir * SB * HID + (size_t)r * HID);
    cvt8(src, dst, threadIdx.x);   // 128 threads x 8 elems = 1024
}

// ---------------------------------------------------------------------------
// fp16 GEMM: C[M,N] = A[M,K]*B[N,K]^T + bias
// 128x256x32 CTA tile, 256 threads, 3-stage cp.async pipeline.
// ---------------------------------------------------------------------------
#define SSTR 40
#define A_ST (128 * SSTR)
#define B_ST (256 * SSTR)
#define STG  (A_ST + B_ST)
#define GSMEM (3 * STG * 2)

__global__ void __launch_bounds__(256, 1) k_gemm(
    const __half* __restrict__ A, const __half* __restrict__ B,
    const float* __restrict__ bias, float* __restrict__ C, int N, int K)
{
    extern __shared__ __half sm[];
    const int tid = threadIdx.x, wid = tid >> 5, lane = tid & 31;
    const int wm = (wid & 1) * 64, wn = (wid >> 1) * 64;
    const int m0 = blockIdx.x * 128, n0 = blockIdx.y * 256;

    float acc[4][8][4];
#pragma unroll
    for (int mi = 0; mi < 4; mi++)
#pragma unroll
        for (int ni = 0; ni < 8; ni++)
#pragma unroll
            for (int q = 0; q < 4; q++) acc[mi][ni][q] = 0.f;

    const int ar = ((lane >> 3) & 1) * 8 + (lane & 7);
    const int acb = (lane >> 4) * 8;
    uint32_t a_sm[4];
#pragma unroll
    for (int mi = 0; mi < 4; mi++)
        a_sm[mi] = sm_u32(&sm[(wm + mi * 16 + ar) * SSTR + acb]);
    const int br = (lane >> 4) * 8 + (lane & 7);
    const int bcb = ((lane >> 3) & 1) * 8;
    uint32_t b_sm[4];
#pragma unroll
    for (int nj = 0; nj < 4; nj++)
        b_sm[nj] = sm_u32(&sm[A_ST + (wn + nj * 16 + br) * SSTR + bcb]);

    const int lr = tid >> 2, lc = (tid & 3) * 8;
    const __half* Ag = A + (size_t)(m0 + lr) * K + lc;
    const __half* Bg = B + (size_t)(n0 + lr) * K + lc;
    const uint32_t sA = sm_u32(&sm[lr * SSTR + lc]);
    const uint32_t sB = sm_u32(&sm[A_ST + lr * SSTR + lc]);

    const int niter = K >> 5;

#define LOAD_STAGE(s)                                                          \
    do {                                                                       \
        const uint32_t off_ = (uint32_t)((s) % 3) * (STG * 2);                 \
        const int k0_ = (s) << 5;                                              \
        cp16s(sA + off_,                    Ag + k0_);                         \
        cp16s(sA + off_ + 64 * SSTR * 2,    Ag + (size_t)64 * K + k0_);        \
        cp16s(sB + off_,                    Bg + k0_);                         \
        cp16s(sB + off_ + 64 * SSTR * 2,    Bg + (size_t)64 * K + k0_);        \
        cp16s(sB + off_ + 128 * SSTR * 2,   Bg + (size_t)128 * K + k0_);       \
        cp16s(sB + off_ + 192 * SSTR * 2,   Bg + (size_t)192 * K + k0_);       \
    } while (0)

    LOAD_STAGE(0);
    CP_COMMIT();
    if (niter > 1) { LOAD_STAGE(1); }
    CP_COMMIT();

    for (int it = 0; it < niter; it++) {
        CP_WAIT1();
        __syncthreads();
        const uint32_t off = (uint32_t)(it % 3) * (STG * 2);
#pragma unroll
        for (int kk = 0; kk < 2; kk++) {
            uint32_t af[4][4], bf[4][4];
#pragma unroll
            for (int mi = 0; mi < 4; mi++) ldsm4(af[mi], a_sm[mi] + off + kk * 32);
#pragma unroll
            for (int nj = 0; nj < 4; nj++) ldsm4(bf[nj], b_sm[nj] + off + kk * 32);
#pragma unroll
            for (int mi = 0; mi < 4; mi++)
#pragma unroll
                for (int ni = 0; ni < 8; ni++)
                    mma16816(acc[mi][ni], af[mi],
                             bf[ni >> 1][(ni & 1) * 2], bf[ni >> 1][(ni & 1) * 2 + 1]);
        }
        if (it + 2 < niter) { LOAD_STAGE(it + 2); }
        CP_COMMIT();
    }
#undef LOAD_STAGE

    const int g = lane >> 2, t2 = (lane & 3) * 2;
#pragma unroll
    for (int mi = 0; mi < 4; mi++)
#pragma unroll
        for (int ni = 0; ni < 8; ni++) {
            int row = m0 + wm + mi * 16 + g;
            int col = n0 + wn + ni * 8 + t2;
            float b0 = bias[col], b1 = bias[col + 1];
            float2 r0 = make_float2(acc[mi][ni][0] + b0, acc[mi][ni][1] + b1);
            *reinterpret_cast<float2*>(&C[(size_t)row * N + col]) = r0;
            float2 r1 = make_float2(acc[mi][ni][2] + b0, acc[mi][ni][3] + b1);
            *reinterpret_cast<float2*>(&C[(size_t)(row + 8) * N + col]) = r1;
        }
}

// ---------------------------------------------------------------------------
// Persistent GRU + overlapped wdec conversion.
// Grid 148: CTAs 0..127 run the GRU (64 per direction); CTAs 128..147 convert
// Wdec fp32->fp16 on the otherwise-idle SMs (GRU is latency-bound, not BW).
// ---------------------------------------------------------------------------
#define SPAD 1032
#define GRU_CTAS 128
#define CVT_CTAS 20

__global__ void __launch_bounds__(384, 1) k_gru(
    const float* __restrict__ bhh_l, const float* __restrict__ bhh_r,
    const float* __restrict__ wdec_src)
{
    const int tid = threadIdx.x;

    if (blockIdx.x >= GRU_CTAS) {
        // wdec fp32 -> fp16 (overlapped with the recurrence)
        const float4* s4 = reinterpret_cast<const float4*>(wdec_src);
        uint4* d4 = reinterpret_cast<uint4*>(g_wdec);
        int i = (blockIdx.x - GRU_CTAS) * 384 + tid;
        const int st = CVT_CTAS * 384;
        const int n8 = NTOK * 2 * HID / 8;
        for (; i < n8; i += st) cvt8(s4, d4, i);
        return;
    }

    const int dir = blockIdx.x >> 6;
    const int j0  = (blockIdx.x & 63) * 16;
    const float* bhh = dir ? bhh_r : bhh_l;

    __shared__ __half As[16 * SPAD];
    __shared__ float red[12][16][8];

    const int wid = tid >> 5, lane = tid & 31;
    const int gw = wid % 6, kh = wid / 6;
    const int gate = gw >> 1, jh = gw & 1;
    const int g = lane >> 2, t2 = (lane & 3) * 2;
    const int nrow = gate * HID + j0 + jh * 8 + g;
    const int kbase = kh * 512;

    uint32_t rb0[32], rb1[32];
    const __half* wr = g_whh[dir] + (size_t)nrow * HID + kbase + t2;
#pragma unroll
    for (int c = 0; c < 32; c++) {
        rb0[c] = *reinterpret_cast<const uint32_t*>(wr + c * 16);
        rb1[c] = *reinterpret_cast<const uint32_t*>(wr + c * 16 + 8);
    }

    const int ar = ((lane >> 3) & 1) * 8 + (lane & 7);
    const uint32_t a_sm = (uint32_t)__cvta_generic_to_shared(
        &As[ar * SPAD + (lane >> 4) * 8 + kbase]);

    __half* hw = g_h[dir];
    unsigned* barp = &g_bar[dir];
    const float* xgp = g_xg[dir];

#pragma unroll 1
    for (int s = 0; s < S_LEN; s++) {
        const int cur = s & 1;
        const uint4* hsrc = reinterpret_cast<const uint4*>(hw + cur * BATCH * HID);
        for (int i = tid; i < 2048; i += 384) {
            int r = i >> 7, c8 = (i & 127) * 8;
            *reinterpret_cast<uint4*>(&As[r * SPAD + c8]) = __ldcg(&hsrc[r * 128 + (i & 127)]);
        }
        __syncthreads();

        float acc[4] = {0.f, 0.f, 0.f, 0.f};
#pragma unroll
        for (int c = 0; c < 32; c++) {
            uint32_t af[4];
            ldsm4(af, a_sm + c * 32);
            mma16816(acc, af, rb0[c], rb1[c]);
        }
        red[wid][g][t2]         = acc[0];
        red[wid][g][t2 + 1]     = acc[1];
        red[wid][g + 8][t2]     = acc[2];
        red[wid][g + 8][t2 + 1] = acc[3];
        __syncthreads();

        for (int idx = tid; idx < 256; idx += 384) {
            int b = idx >> 4, jj = idx & 15, j = j0 + jj;
            int w0 = jj >> 3, c7 = jj & 7;
            float hr = red[w0][b][c7]      + red[6 + w0][b][c7]  + bhh[j];
            float hz = red[2 + w0][b][c7]  + red[8 + w0][b][c7]  + bhh[HID + j];
            float hn = red[4 + w0][b][c7]  + red[10 + w0][b][c7] + bhh[2 * HID + j];
            const float* xr = &xgp[(size_t)(s * 16 + b) * G3 + j];
            float r = 1.f / (1.f + expf(-(xr[0] + hr)));
            float z = 1.f / (1.f + expf(-(xr[HID] + hz)));
            float n = tanhf(xr[2 * HID] + r * hn);
            float hp = __half2float(As[b * SPAD + j]);
            float h = (1.f - z) * n + z * hp;
            hw[(cur ^ 1) * BATCH * HID + b * HID + j] = __float2half(h);
            g_outh[dir][(s * 16 + b) * HID + j] = __float2half(h);
        }
        __syncthreads();

        if (tid == 0) {
            __threadfence();
            atomicAdd(barp, 1u);
            unsigned tgt = 64u * (unsigned)(s + 1);
            while (*(volatile unsigned*)barp < tgt) __nanosleep(64);
        }
        __syncthreads();
    }
}

// ---------------------------------------------------------------------------
// Attention scores / exp / cumulative context
// ---------------------------------------------------------------------------
__global__ void k_score(const float* __restrict__ tmp,
                        const float* __restrict__ vl, const float* __restrict__ bvl,
                        const float* __restrict__ vr, const float* __restrict__ bvr,
                        float* __restrict__ sc) {
    int dir = blockIdx.x >> 9;
    int row = (blockIdx.x & 511) * 8 + (threadIdx.x >> 5);
    int lane = threadIdx.x & 31;
    const float* v = dir ? vr : vl;
    float bv = dir ? bvr[0] : bvl[0];
    const float* t = tmp + (size_t)dir * SB * HID + (size_t)row * HID;
    float s = 0.f;
    for (int j = lane; j < HID; j += 32) s += tanhf(t[j]) * v[j];
#pragma unroll
    for (int o = 16; o; o >>= 1) s += __shfl_xor_sync(0xffffffffu, s, o);
    if (lane == 0) sc[dir * SB + row] = s + bv;
}

__global__ void k_e(float* __restrict__ sc) {
    int dir = blockIdx.x >> 4, b = blockIdx.x & 15, lane = threadIdx.x;
    float v[8];
    float m = -1e30f;
#pragma unroll
    for (int i = 0; i < 8; i++) {
        v[i] = sc[dir * SB + (lane * 8 + i) * 16 + b];
        m = fmaxf(m, v[i]);
    }
#pragma unroll
    for (int o = 16; o; o >>= 1) m = fmaxf(m, __shfl_xor_sync(0xffffffffu, m, o));
#pragma unroll
    for (int i = 0; i < 8; i++)
        sc[dir * SB + (lane * 8 + i) * 16 + b] = expf(v[i] - m);
}

__global__ void k_cumsum(const float* __restrict__ sc,
                         const __half* __restrict__ outh, __half* __restrict__ ctx) {
    int bid = blockIdx.x;
    int dir = bid >> 7, rem = bid & 127;
    int b = rem >> 3, chunk = rem & 7;
    int j = chunk * 128 + threadIdx.x;
    float acc = 0.f, den = 0.f;
    for (int s = 0; s < S_LEN; s++) {
        float e = sc[dir * SB + s * 16 + b];
        float o = __half2float(outh[(size_t)dir * SB * HID + (s * 16 + b) * HID + j]);
        acc += e * o;
        den += e;
        int row = dir ? (S_LEN - 1 - s) : s;
        ctx[(size_t)(row * 16 + b) * 2 * HID + dir * HID + j] = __float2half(acc / den);
    }
}

// ---------------------------------------------------------------------------
// Launch sequence. Order chosen so the 6th launch (ncu -s 5 -c 1 capture
// window) is the xg GEMM — gives a real GEMM profile next round.
// ---------------------------------------------------------------------------
extern "C" void kernel_launch(void* const* d_in, const int* in_sizes, int n_in,
                              void* d_out, int out_size) {
    const int*   dl      = (const int*)d_in[0];
    const int*   dr      = (const int*)d_in[1];
    const float* hl      = (const float*)d_in[2];
    const float* hr      = (const float*)d_in[3];
    const float* emb     = (const float*)d_in[4];
    const float* wih_l   = (const float*)d_in[5];
    const float* whh_l   = (const float*)d_in[6];
    const float* bih_l   = (const float*)d_in[7];
    const float* bhh_l   = (const float*)d_in[8];
    const float* wih_r   = (const float*)d_in[9];
    const float* whh_r   = (const float*)d_in[10];
    const float* bih_r   = (const float*)d_in[11];
    const float* bhh_r   = (const float*)d_in[12];
    const float* wattn_l = (const float*)d_in[13];
    const float* battn_l = (const float*)d_in[14];
    const float* vl      = (const float*)d_in[15];
    const float* bvl     = (const float*)d_in[16];
    const float* wattn_r = (const float*)d_in[17];
    const float* battn_r = (const float*)d_in[18];
    const float* vr      = (const float*)d_in[19];
    const float* bvr     = (const float*)d_in[20];
    const float* wdec    = (const float*)d_in[21];
    const float* bdec    = (const float*)d_in[22];
    float* out = (float*)d_out;

    void* p;
    cudaGetSymbolAddress(&p, g_wih);   __half* wih    = (__half*)p;
    cudaGetSymbolAddress(&p, g_whh);   __half* whh    = (__half*)p;
    cudaGetSymbolAddress(&p, g_wattn); __half* wattn  = (__half*)p;
    cudaGetSymbolAddress(&p, g_wdec);  __half* wdec16 = (__half*)p;
    cudaGetSymbolAddress(&p, g_xemb);  __half* xemb   = (__half*)p;
    cudaGetSymbolAddress(&p, g_xg);    float*  xg     = (float*)p;
    cudaGetSymbolAddress(&p, g_outh);  __half* outh   = (__half*)p;
    cudaGetSymbolAddress(&p, g_tmp);   float*  tmp    = (float*)p;
    cudaGetSymbolAddress(&p, g_sc);    float*  sc     = (float*)p;
    cudaGetSymbolAddress(&p, g_ctx);   __half* ctx    = (__half*)p;

    cudaFuncSetAttribute(k_gemm, cudaFuncAttributeMaxDynamicSharedMemorySize, GSMEM);

    // 1-5: prerequisites of xg_l
    k_cvt<<<768, 256>>>(wih_l, wih, G3 * HID / 8);                 // 1
    k_embed<<<8192, 128>>>(dl, dr, emb, xemb);                     // 2
    k_hinit<<<1, 256>>>(hl, hr);                                   // 3
    k_cvt<<<768, 256>>>(whh_l, whh, G3 * HID / 8);                 // 4
    k_cvt<<<768, 256>>>(wih_r, wih + G3 * HID, G3 * HID / 8);      // 5
    // 6: PROFILED LAUNCH — xg_l GEMM [4096,3072,1024]
    k_gemm<<<dim3(32, 12), 256, GSMEM>>>(xemb, wih, bih_l, xg, G3, HID);
    k_cvt<<<768, 256>>>(whh_r, whh + G3 * HID, G3 * HID / 8);      // 7
    k_gemm<<<dim3(32, 12), 256, GSMEM>>>(xemb + SB * HID, wih + G3 * HID,
                                         bih_r, xg + (size_t)SB * G3, G3, HID);
    k_cvt<<<512, 256>>>(wattn_l, wattn, HID * HID / 8);
    k_cvt<<<512, 256>>>(wattn_r, wattn + HID * HID, HID * HID / 8);

    // GRU + overlapped wdec conversion
    k_gru<<<GRU_CTAS + CVT_CTAS, 384>>>(bhh_l, bhh_r, wdec);

    // tmp[dir] = outh[dir] @ Wattn^T + battn   [4096, 1024]
    k_gemm<<<dim3(32, 4), 256, GSMEM>>>(outh, wattn, battn_l, tmp, HID, HID);
    k_gemm<<<dim3(32, 4), 256, GSMEM>>>(outh + SB * HID, wattn + HID * HID,
                                        battn_r, tmp + SB * HID, HID, HID);

    k_score<<<1024, 256>>>(tmp, vl, bvl, vr, bvr, sc);
    k_e<<<32, 32>>>(sc);
    k_cumsum<<<256, 128>>>(sc, outh, ctx);

    // decoded = ctx @ Wdec^T + bdec   [4096, 32000]
    k_gemm<<<dim3(32, 125), 256, GSMEM>>>(ctx, wdec16, bdec, out, NTOK, 2 * HID);
}

// round 11
// speedup vs baseline: 1.0574x; 1.0402x over previous
#include <cuda_runtime.h>
#include <cuda_fp16.h>
#include <cstdint>

#define S_LEN 256
#define BATCH 16
#define HID   1024
#define G3    3072
#define SB    4096
#define NTOK  32000

// ---------------------------------------------------------------------------
// Static scratch (allocation-free per harness rules)
// ---------------------------------------------------------------------------
__device__ __half g_wih[2][G3 * HID];
__device__ __half g_whh[2][G3 * HID];
__device__ __half g_wattn[2][HID * HID];
__device__ __half g_wdec[(size_t)NTOK * 2 * HID];
__device__ __half g_xemb[2][SB * HID];
__device__ float  g_xg[2][(size_t)SB * G3];
__device__ __half g_outh[2][SB * HID];
__device__ float  g_tmp[2][(size_t)SB * HID];
__device__ float  g_sc[2][SB];
__device__ __half g_ctx[(size_t)SB * 2 * HID];
__device__ __half g_h[2][2 * BATCH * HID];
__device__ unsigned g_bar[2];

// ---------------------------------------------------------------------------
// Primitives (mma.sync / ldmatrix / cp.async — tcgen05 unavailable on the
// bench's compute_103 virtual target, confirmed R7)
// ---------------------------------------------------------------------------
__device__ __forceinline__ uint32_t sm_u32(const void* p) {
    return (uint32_t)__cvta_generic_to_shared(p);
}

__device__ __forceinline__ void mma16816(float* c, const uint32_t* a,
                                         uint32_t b0, uint32_t b1) {
    asm volatile(
        "mma.sync.aligned.m16n8k16.row.col.f32.f16.f16.f32 "
        "{%0,%1,%2,%3}, {%4,%5,%6,%7}, {%8,%9}, {%0,%1,%2,%3};"
        : "+f"(c[0]), "+f"(c[1]), "+f"(c[2]), "+f"(c[3])
        : "r"(a[0]), "r"(a[1]), "r"(a[2]), "r"(a[3]), "r"(b0), "r"(b1));
}

__device__ __forceinline__ void ldsm4(uint32_t* r, uint32_t addr) {
    asm volatile(
        "ldmatrix.sync.aligned.m8n8.x4.shared.b16 {%0,%1,%2,%3}, [%4];"
        : "=r"(r[0]), "=r"(r[1]), "=r"(r[2]), "=r"(r[3]) : "r"(addr));
}

__device__ __forceinline__ void cp16s(uint32_t s, const void* g) {
    asm volatile("cp.async.cg.shared.global [%0], [%1], 16;" :: "r"(s), "l"(g));
}
#define CP_COMMIT() asm volatile("cp.async.commit_group;" ::: "memory")
#define CP_WAIT1()  asm volatile("cp.async.wait_group 1;" ::: "memory")

// ---------------------------------------------------------------------------
// fp32 -> fp16 conversion: 8 elems/thread, LDG.128 x2 + STG.128 x1
// ---------------------------------------------------------------------------
__device__ __forceinline__ void cvt8(const float4* __restrict__ s4,
                                     uint4* __restrict__ d4, int i) {
    float4 a = s4[2 * i], b = s4[2 * i + 1];
    __half2 h0 = __floats2half2_rn(a.x, a.y);
    __half2 h1 = __floats2half2_rn(a.z, a.w);
    __half2 h2 = __floats2half2_rn(b.x, b.y);
    __half2 h3 = __floats2half2_rn(b.z, b.w);
    uint4 o;
    o.x = *reinterpret_cast<uint32_t*>(&h0);
    o.y = *reinterpret_cast<uint32_t*>(&h1);
    o.z = *reinterpret_cast<uint32_t*>(&h2);
    o.w = *reinterpret_cast<uint32_t*>(&h3);
    d4[i] = o;
}

__global__ void k_cvt(const float* __restrict__ src, __half* __restrict__ dst, int n8) {
    int i = blockIdx.x * blockDim.x + threadIdx.x;
    int st = gridDim.x * blockDim.x;
    const float4* s4 = reinterpret_cast<const float4*>(src);
    uint4* d4 = reinterpret_cast<uint4*>(dst);
    for (; i < n8; i += st) cvt8(s4, d4, i);
}

__global__ void k_hinit(const float* __restrict__ hl, const float* __restrict__ hr) {
    int t = threadIdx.x;
    if (t < 2) g_bar[t] = 0u;
    for (int i = t; i < BATCH * HID; i += blockDim.x) {
        g_h[0][i] = __float2half(hl[i]);
        g_h[1][i] = __float2half(hr[i]);
    }
}

__global__ void k_embed(const int* __restrict__ dl, const int* __restrict__ dr,
                        const float* __restrict__ emb, __half* __restrict__ xemb) {
    int row = blockIdx.x;
    int dir = row >> 12;
    int r   = row & (SB - 1);
    int s   = r >> 4, b = r & 15;
    int tok = dir ? dr[(S_LEN - 1 - s) * BATCH + b] : dl[r];
    const float4* src = reinterpret_cast<const float4*>(emb + (size_t)tok * HID);
    uint4* dst = reinterpret_cast<uint4*>(xemb + (size_t)dir * SB * HID + (size_t)r * HID);
    cvt8(src, dst, threadIdx.x);
}

// ---------------------------------------------------------------------------
// fp16 GEMM: C[M,N] = A[M,K]*B[N,K]^T + bias
// 128x256x64 CTA tile, 512 threads (4x4 warp grid, 32x64 warp tiles),
// 3-stage cp.async pipeline, one __syncthreads per 64-K iter.
// Requires M%128==0, N%256==0, K%64==0.
// ---------------------------------------------------------------------------
#define SSTR 72                       // halfs per SMEM row (64 + 8 pad)
#define A_ROWS 128
#define B_ROWS 256
#define STG ((A_ROWS + B_ROWS) * SSTR)    // halfs per stage = 27648
#define GSMEM (3 * STG * 2)               // 165888 B

__global__ void __launch_bounds__(512, 1) k_gemm(
    const __half* __restrict__ A, const __half* __restrict__ B,
    const float* __restrict__ bias, float* __restrict__ C, int N, int K)
{
    extern __shared__ __half sm[];
    const int tid = threadIdx.x, wid = tid >> 5, lane = tid & 31;
    const int wm = (wid & 3) * 32, wn = (wid >> 2) * 64;
    const int m0 = blockIdx.x * 128, n0 = blockIdx.y * 256;

    float acc[2][8][4];
#pragma unroll
    for (int mi = 0; mi < 2; mi++)
#pragma unroll
        for (int ni = 0; ni < 8; ni++)
#pragma unroll
            for (int q = 0; q < 4; q++) acc[mi][ni][q] = 0.f;

    const uint32_t smb = sm_u32(sm);

    // ldmatrix addresses (stage 0); add byte stage offset per iter
    const int ar = ((lane >> 3) & 1) * 8 + (lane & 7);
    const int acb = (lane >> 4) * 8;
    uint32_t a_sm[2];
#pragma unroll
    for (int mi = 0; mi < 2; mi++)
        a_sm[mi] = smb + ((wm + mi * 16 + ar) * SSTR + acb) * 2;
    const int br = (lane >> 4) * 8 + (lane & 7);
    const int bcb = ((lane >> 3) & 1) * 8;
    uint32_t b_sm[4];
#pragma unroll
    for (int nj = 0; nj < 4; nj++)
        b_sm[nj] = smb + ((A_ROWS + wn + nj * 16 + br) * SSTR + bcb) * 2;

    const __half* Ag = A + (size_t)m0 * K;
    const __half* Bg = B + (size_t)n0 * K;
    const int niter = K >> 6;

#define LOAD_STAGE(s)                                                          \
    do {                                                                       \
        const uint32_t off_ = (uint32_t)((s) % 3) * (STG * 2);                 \
        const int k0_ = (s) << 6;                                              \
        _Pragma("unroll")                                                      \
        for (int j = 0; j < 6; j++) {                                          \
            int u = tid + j * 512;                                             \
            int r = u >> 3, sub = (u & 7) * 8;                                 \
            uint32_t sa = smb + off_ + (uint32_t)(r * SSTR + sub) * 2;         \
            const __half* gp = (r < A_ROWS)                                    \
                ? Ag + (size_t)r * K + k0_ + sub                               \
                : Bg + (size_t)(r - A_ROWS) * K + k0_ + sub;                   \
            cp16s(sa, gp);                                                     \
        }                                                                      \
    } while (0)

    LOAD_STAGE(0);
    CP_COMMIT();
    if (niter > 1) { LOAD_STAGE(1); }
    CP_COMMIT();

    for (int it = 0; it < niter; it++) {
        CP_WAIT1();
        __syncthreads();
        const uint32_t off = (uint32_t)(it % 3) * (STG * 2);
#pragma unroll
        for (int kk = 0; kk < 4; kk++) {
            uint32_t af[2][4], bf[4][4];
#pragma unroll
            for (int mi = 0; mi < 2; mi++) ldsm4(af[mi], a_sm[mi] + off + kk * 32);
#pragma unroll
            for (int nj = 0; nj < 4; nj++) ldsm4(bf[nj], b_sm[nj] + off + kk * 32);
#pragma unroll
            for (int mi = 0; mi < 2; mi++)
#pragma unroll
                for (int ni = 0; ni < 8; ni++)
                    mma16816(acc[mi][ni], af[mi],
                             bf[ni >> 1][(ni & 1) * 2], bf[ni >> 1][(ni & 1) * 2 + 1]);
        }
        if (it + 2 < niter) { LOAD_STAGE(it + 2); }
        CP_COMMIT();
    }
#undef LOAD_STAGE

    const int g = lane >> 2, t2 = (lane & 3) * 2;
#pragma unroll
    for (int mi = 0; mi < 2; mi++)
#pragma unroll
        for (int ni = 0; ni < 8; ni++) {
            int row = m0 + wm + mi * 16 + g;
            int col = n0 + wn + ni * 8 + t2;
            float b0 = bias[col], b1 = bias[col + 1];
            float2 r0 = make_float2(acc[mi][ni][0] + b0, acc[mi][ni][1] + b1);
            *reinterpret_cast<float2*>(&C[(size_t)row * N + col]) = r0;
            float2 r1 = make_float2(acc[mi][ni][2] + b0, acc[mi][ni][3] + b1);
            *reinterpret_cast<float2*>(&C[(size_t)(row + 8) * N + col]) = r1;
        }
}

// ---------------------------------------------------------------------------
// Persistent GRU + overlapped wdec conversion (unchanged from R9).
// ---------------------------------------------------------------------------
#define SPAD 1032
#define GRU_CTAS 128
#define CVT_CTAS 20

__global__ void __launch_bounds__(384, 1) k_gru(
    const float* __restrict__ bhh_l, const float* __restrict__ bhh_r,
    const float* __restrict__ wdec_src)
{
    const int tid = threadIdx.x;

    if (blockIdx.x >= GRU_CTAS) {
        const float4* s4 = reinterpret_cast<const float4*>(wdec_src);
        uint4* d4 = reinterpret_cast<uint4*>(g_wdec);
        int i = (blockIdx.x - GRU_CTAS) * 384 + tid;
        const int st = CVT_CTAS * 384;
        const int n8 = NTOK * 2 * HID / 8;
        for (; i < n8; i += st) cvt8(s4, d4, i);
        return;
    }

    const int dir = blockIdx.x >> 6;
    const int j0  = (blockIdx.x & 63) * 16;
    const float* bhh = dir ? bhh_r : bhh_l;

    __shared__ __half As[16 * SPAD];
    __shared__ float red[12][16][8];

    const int wid = tid >> 5, lane = tid & 31;
    const int gw = wid % 6, kh = wid / 6;
    const int gate = gw >> 1, jh = gw & 1;
    const int g = lane >> 2, t2 = (lane & 3) * 2;
    const int nrow = gate * HID + j0 + jh * 8 + g;
    const int kbase = kh * 512;

    uint32_t rb0[32], rb1[32];
    const __half* wr = g_whh[dir] + (size_t)nrow * HID + kbase + t2;
#pragma unroll
    for (int c = 0; c < 32; c++) {
        rb0[c] = *reinterpret_cast<const uint32_t*>(wr + c * 16);
        rb1[c] = *reinterpret_cast<const uint32_t*>(wr + c * 16 + 8);
    }

    const int ar = ((lane >> 3) & 1) * 8 + (lane & 7);
    const uint32_t a_sm = (uint32_t)__cvta_generic_to_shared(
        &As[ar * SPAD + (lane >> 4) * 8 + kbase]);

    __half* hw = g_h[dir];
    unsigned* barp = &g_bar[dir];
    const float* xgp = g_xg[dir];

#pragma unroll 1
    for (int s = 0; s < S_LEN; s++) {
        const int cur = s & 1;
        const uint4* hsrc = reinterpret_cast<const uint4*>(hw + cur * BATCH * HID);
        for (int i = tid; i < 2048; i += 384) {
            int r = i >> 7, c8 = (i & 127) * 8;
            *reinterpret_cast<uint4*>(&As[r * SPAD + c8]) = __ldcg(&hsrc[r * 128 + (i & 127)]);
        }
        __syncthreads();

        float acc[4] = {0.f, 0.f, 0.f, 0.f};
#pragma unroll
        for (int c = 0; c < 32; c++) {
            uint32_t af[4];
            ldsm4(af, a_sm + c * 32);
            mma16816(acc, af, rb0[c], rb1[c]);
        }
        red[wid][g][t2]         = acc[0];
        red[wid][g][t2 + 1]     = acc[1];
        red[wid][g + 8][t2]     = acc[2];
        red[wid][g + 8][t2 + 1] = acc[3];
        __syncthreads();

        for (int idx = tid; idx < 256; idx += 384) {
            int b = idx >> 4, jj = idx & 15, j = j0 + jj;
            int w0 = jj >> 3, c7 = jj & 7;
            float hr = red[w0][b][c7]      + red[6 + w0][b][c7]  + bhh[j];
            float hz = red[2 + w0][b][c7]  + red[8 + w0][b][c7]  + bhh[HID + j];
            float hn = red[4 + w0][b][c7]  + red[10 + w0][b][c7] + bhh[2 * HID + j];
            const float* xr = &xgp[(size_t)(s * 16 + b) * G3 + j];
            float r = 1.f / (1.f + expf(-(xr[0] + hr)));
            float z = 1.f / (1.f + expf(-(xr[HID] + hz)));
            float n = tanhf(xr[2 * HID] + r * hn);
            float hp = __half2float(As[b * SPAD + j]);
            float h = (1.f - z) * n + z * hp;
            hw[(cur ^ 1) * BATCH * HID + b * HID + j] = __float2half(h);
            g_outh[dir][(s * 16 + b) * HID + j] = __float2half(h);
        }
        __syncthreads();

        if (tid == 0) {
            __threadfence();
            atomicAdd(barp, 1u);
            unsigned tgt = 64u * (unsigned)(s + 1);
            while (*(volatile unsigned*)barp < tgt) __nanosleep(64);
        }
        __syncthreads();
    }
}

// ---------------------------------------------------------------------------
// Attention scores / exp / cumulative context
// ---------------------------------------------------------------------------
__global__ void k_score(const float* __restrict__ tmp,
                        const float* __restrict__ vl, const float* __restrict__ bvl,
                        const float* __restrict__ vr, const float* __restrict__ bvr,
                        float* __restrict__ sc) {
    int dir = blockIdx.x >> 9;
    int row = (blockIdx.x & 511) * 8 + (threadIdx.x >> 5);
    int lane = threadIdx.x & 31;
    const float* v = dir ? vr : vl;
    float bv = dir ? bvr[0] : bvl[0];
    const float* t = tmp + (size_t)dir * SB * HID + (size_t)row * HID;
    float s = 0.f;
    for (int j = lane; j < HID; j += 32) s += tanhf(t[j]) * v[j];
#pragma unroll
    for (int o = 16; o; o >>= 1) s += __shfl_xor_sync(0xffffffffu, s, o);
    if (lane == 0) sc[dir * SB + row] = s + bv;
}

__global__ void k_e(float* __restrict__ sc) {
    int dir = blockIdx.x >> 4, b = blockIdx.x & 15, lane = threadIdx.x;
    float v[8];
    float m = -1e30f;
#pragma unroll
    for (int i = 0; i < 8; i++) {
        v[i] = sc[dir * SB + (lane * 8 + i) * 16 + b];
        m = fmaxf(m, v[i]);
    }
#pragma unroll
    for (int o = 16; o; o >>= 1) m = fmaxf(m, __shfl_xor_sync(0xffffffffu, m, o));
#pragma unroll
    for (int i = 0; i < 8; i++)
        sc[dir * SB + (lane * 8 + i) * 16 + b] = expf(v[i] - m);
}

__global__ void k_cumsum(const float* __restrict__ sc,
                         const __half* __restrict__ outh, __half* __restrict__ ctx) {
    int bid = blockIdx.x;
    int dir = bid >> 7, rem = bid & 127;
    int b = rem >> 3, chunk = rem & 7;
    int j = chunk * 128 + threadIdx.x;
    float acc = 0.f, den = 0.f;
    for (int s = 0; s < S_LEN; s++) {
        float e = sc[dir * SB + s * 16 + b];
        float o = __half2float(outh[(size_t)dir * SB * HID + (s * 16 + b) * HID + j]);
        acc += e * o;
        den += e;
        int row = dir ? (S_LEN - 1 - s) : s;
        ctx[(size_t)(row * 16 + b) * 2 * HID + dir * HID + j] = __float2half(acc / den);
    }
}

// ---------------------------------------------------------------------------
// Launch sequence. Launches #5 and #6 are both xg GEMMs so the ncu window
// (-s 5 -c 1, possibly offset by the harness's d_out memset) hits a GEMM.
// ---------------------------------------------------------------------------
extern "C" void kernel_launch(void* const* d_in, const int* in_sizes, int n_in,
                              void* d_out, int out_size) {
    const int*   dl      = (const int*)d_in[0];
    const int*   dr      = (const int*)d_in[1];
    const float* hl      = (const float*)d_in[2];
    const float* hr      = (const float*)d_in[3];
    const float* emb     = (const float*)d_in[4];
    const float* wih_l   = (const float*)d_in[5];
    const float* whh_l   = (const float*)d_in[6];
    const float* bih_l   = (const float*)d_in[7];
    const float* bhh_l   = (const float*)d_in[8];
    const float* wih_r   = (const float*)d_in[9];
    const float* whh_r   = (const float*)d_in[10];
    const float* bih_r   = (const float*)d_in[11];
    const float* bhh_r   = (const float*)d_in[12];
    const float* wattn_l = (const float*)d_in[13];
    const float* battn_l = (const float*)d_in[14];
    const float* vl      = (const float*)d_in[15];
    const float* bvl     = (const float*)d_in[16];
    const float* wattn_r = (const float*)d_in[17];
    const float* battn_r = (const float*)d_in[18];
    const float* vr      = (const float*)d_in[19];
    const float* bvr     = (const float*)d_in[20];
    const float* wdec    = (const float*)d_in[21];
    const float* bdec    = (const float*)d_in[22];
    float* out = (float*)d_out;

    void* p;
    cudaGetSymbolAddress(&p, g_wih);   __half* wih    = (__half*)p;
    cudaGetSymbolAddress(&p, g_whh);   __half* whh    = (__half*)p;
    cudaGetSymbolAddress(&p, g_wattn); __half* wattn  = (__half*)p;
    cudaGetSymbolAddress(&p, g_wdec);  __half* wdec16 = (__half*)p;
    cudaGetSymbolAddress(&p, g_xemb);  __half* xemb   = (__half*)p;
    cudaGetSymbolAddress(&p, g_xg);    float*  xg     = (float*)p;
    cudaGetSymbolAddress(&p, g_outh);  __half* outh   = (__half*)p;
    cudaGetSymbolAddress(&p, g_tmp);   float*  tmp    = (float*)p;
    cudaGetSymbolAddress(&p, g_sc);    float*  sc     = (float*)p;
    cudaGetSymbolAddress(&p, g_ctx);   __half* ctx    = (__half*)p;

    cudaFuncSetAttribute(k_gemm, cudaFuncAttributeMaxDynamicSharedMemorySize, GSMEM);

    k_cvt<<<768, 256>>>(wih_l, wih, G3 * HID / 8);                 // 1
    k_cvt<<<768, 256>>>(wih_r, wih + G3 * HID, G3 * HID / 8);      // 2
    k_embed<<<8192, 128>>>(dl, dr, emb, xemb);                     // 3
    k_hinit<<<1, 256>>>(hl, hr);                                   // 4
    // 5 & 6: xg GEMMs [4096,3072,1024] — one of these gets profiled
    k_gemm<<<dim3(32, 12), 512, GSMEM>>>(xemb, wih, bih_l, xg, G3, HID);
    k_gemm<<<dim3(32, 12), 512, GSMEM>>>(xemb + SB * HID, wih + G3 * HID,
                                         bih_r, xg + (size_t)SB * G3, G3, HID);
    k_cvt<<<768, 256>>>(whh_l, whh, G3 * HID / 8);                 // 7
    k_cvt<<<768, 256>>>(whh_r, whh + G3 * HID, G3 * HID / 8);      // 8
    k_cvt<<<512, 256>>>(wattn_l, wattn, HID * HID / 8);            // 9
    k_cvt<<<512, 256>>>(wattn_r, wattn + HID * HID, HID * HID / 8);// 10

    // GRU + overlapped wdec conversion
    k_gru<<<GRU_CTAS + CVT_CTAS, 384>>>(bhh_l, bhh_r, wdec);

    // tmp[dir] = outh[dir] @ Wattn^T + battn   [4096, 1024]
    k_gemm<<<dim3(32, 4), 512, GSMEM>>>(outh, wattn, battn_l, tmp, HID, HID);
    k_gemm<<<dim3(32, 4), 512, GSMEM>>>(outh + SB * HID, wattn + HID * HID,
                                        battn_r, tmp + SB * HID, HID, HID);

    k_score<<<1024, 256>>>(tmp, vl, bvl, vr, bvr, sc);
    k_e<<<32, 32>>>(sc);
    k_cumsum<<<256, 128>>>(sc, outh, ctx);

    // decoded = ctx @ Wdec^T + bdec   [4096, 32000]
    k_gemm<<<dim3(32, 125), 512, GSMEM>>>(ctx, wdec16, bdec, out, NTOK, 2 * HID);
}